// round 17
// baseline (speedup 1.0000x reference)
#include <cuda_runtime.h>

// ---------------------------------------------------------------------------
// DisenHAN on GB300 — fp32, restructured, 2-launch pipeline.
// Identity: with one neighbor type, the hete softmax is over a singleton
// => beta == 1 => wp stays ones; routing = 3 iterations of plain per-facet
// softmax attention.
// Launch 1: pre-transform both tables (TU = user_table@Wpre1_user,
//           TI = item_table@Wpre1_item) — serves both branches' layer-1
//           center AND neighbor transforms via gather.
// Launch 2: fully fused per-(branch,b) block: layer-1 routing (16 warps,
//           one site each) -> smem h1 -> W0 matvec from smem -> layer-0
//           routing by warp 0 -> d_out. No intermediate global traffic.
// ---------------------------------------------------------------------------

#define VCAP   100000
#define NB     2048          // batch
#define NS     16            // hop-1 fanout (N0)
#define NN     16            // hop-2 fanout (N1)

#define OFF_TU  0L
#define OFF_TI  ((long)VCAP * 64)
#define SCRATCH_FLOATS ((long)2 * VCAP * 64)

__device__ float g_scratch[SCRATCH_FLOATS];

typedef unsigned long long ull;

__device__ __forceinline__ ull ffma2(ull a, ull b, ull c) {
    ull d;
    asm("fma.rn.f32x2 %0, %1, %2, %3;" : "=l"(d) : "l"(a), "l"(b), "l"(c));
    return d;
}
__device__ __forceinline__ float pairsum(ull x) {
    float lo = __uint_as_float((unsigned)(x & 0xffffffffu));
    float hi = __uint_as_float((unsigned)(x >> 32));
    return lo + hi;
}

// ---------------------------------------------------------------------------
// Two independent O[M,64] = A[M,64] @ W[64,64] problems in one launch.
// Blocks [0, bph) do problem 0; [bph, 2*bph) do problem 1.
// 128 rows/block, 256 threads, 8x4 output tile/thread, fp32x2 FMA with
// d-parity accumulator split (even-d partial in .lo, odd-d in .hi).
// W staged transposed + XOR-swizzled in smem.
// ---------------------------------------------------------------------------
__global__ __launch_bounds__(256) void gemm64x2(
        const float* __restrict__ A0, const float* __restrict__ A1,
        const float* __restrict__ Wp0, const float* __restrict__ Wp1,
        long o0off, long o1off, int M, int bph) {
    __shared__ float sWT[64 * 64];
    __shared__ float sX[128 * 64];

    const int tid = threadIdx.x;
    const bool second = (int)blockIdx.x >= bph;
    const float* __restrict__ W = second ? Wp1 : Wp0;
    const float* __restrict__ A = second ? A1 : A0;
    const long ooff = second ? o1off : o0off;
    const int  row0 = (second ? (int)blockIdx.x - bph : (int)blockIdx.x) * 128;
    float* __restrict__ O = g_scratch + ooff;

    // Stage W transposed + swizzled (coalesced global reads).
#pragma unroll
    for (int e = tid; e < 2048; e += 256) {
        int dp = e >> 6;     // d-pair 0..31
        int c  = e & 63;     // output column
        float w0 = __ldg(&W[(2 * dp) * 64 + c]);
        float w1 = __ldg(&W[(2 * dp) * 64 + 64 + c]);
        int idx = c * 32 + (dp ^ (c >> 2));
        sWT[2 * idx]     = w0;
        sWT[2 * idx + 1] = w1;
    }
    // Load 128x64 A tile (coalesced float4), zero-fill past M.
    {
        float4* sX4 = (float4*)sX;
#pragma unroll
        for (int i = 0; i < 8; i++) {
            int f4 = tid + 256 * i;          // 0..2047
            int r  = f4 >> 4;
            int c4 = f4 & 15;
            float4 v = make_float4(0.f, 0.f, 0.f, 0.f);
            int gr = row0 + r;
            if (gr < M) v = __ldg(((const float4*)A) + (long)gr * 16 + c4);
            sX4[f4] = v;
        }
    }
    __syncthreads();

    const int cg = tid & 15;   // 4-column group
    const int rg = tid >> 4;   // 8-row group
    ull acc[8][4];
#pragma unroll
    for (int i = 0; i < 8; i++)
#pragma unroll
        for (int c = 0; c < 4; c++) acc[i][c] = 0ULL;

    const ull* __restrict__ sWu = (const ull*)sWT + 128 * cg;
    const float* __restrict__ xrow = sX + (8 * rg) * 64;

#pragma unroll 8
    for (int dp = 0; dp < 32; dp++) {
        int sw = dp ^ cg;
        ull w0 = sWu[sw];
        ull w1 = sWu[32 + sw];
        ull w2 = sWu[64 + sw];
        ull w3 = sWu[96 + sw];
#pragma unroll
        for (int i = 0; i < 8; i++) {
            ull a2 = *(const ull*)&xrow[i * 64 + 2 * dp];
            acc[i][0] = ffma2(a2, w0, acc[i][0]);
            acc[i][1] = ffma2(a2, w1, acc[i][1]);
            acc[i][2] = ffma2(a2, w2, acc[i][2]);
            acc[i][3] = ffma2(a2, w3, acc[i][3]);
        }
    }

#pragma unroll
    for (int i = 0; i < 8; i++) {
        int gr = row0 + 8 * rg + i;
        if (gr < M) {
            float4 v;
            v.x = pairsum(acc[i][0]);
            v.y = pairsum(acc[i][1]);
            v.z = pairsum(acc[i][2]);
            v.w = pairsum(acc[i][3]);
            *(float4*)&O[(long)gr * 64 + 4 * cg] = v;
        }
    }
}

// ---------------------------------------------------------------------------
// Routing core (warp-level). 8 facets x 8 dims; lane = (facet k = lane>>2,
// sub = lane&3). Each lane owns the FULL 8-dim facet slice of 4 neighbors
// (n = 4*sub + j) -> dot products need no shuffles. softmax stats and the
// z aggregate reduce across the 4-lane facet group via shfl_xor 1,2.
//   3 iterations of: e = ct.nh/sqrt(8); a = softmax_n e; ht = c + a.nh
// ---------------------------------------------------------------------------
__device__ __forceinline__ void routing_core(const float cf[8], const float nhf[4][8],
                                             float ht[8]) {
    const float CS = 1.4426950408889634f * 0.35355339059327373f;  // log2(e)/sqrt(8)
#pragma unroll
    for (int it = 0; it < 3; it++) {
        float l[4];
#pragma unroll
        for (int j = 0; j < 4; j++) {
            float p = ht[0] * nhf[j][0];
#pragma unroll
            for (int d = 1; d < 8; d++) p = fmaf(ht[d], nhf[j][d], p);
            l[j] = p * CS;   // base-2 logits
        }
        float m = fmaxf(fmaxf(l[0], l[1]), fmaxf(l[2], l[3]));
        m = fmaxf(m, __shfl_xor_sync(0xffffffffu, m, 1));
        m = fmaxf(m, __shfl_xor_sync(0xffffffffu, m, 2));
        float a[4], s = 0.f;
#pragma unroll
        for (int j = 0; j < 4; j++) { a[j] = exp2f(l[j] - m); s += a[j]; }
        s += __shfl_xor_sync(0xffffffffu, s, 1);
        s += __shfl_xor_sync(0xffffffffu, s, 2);
        float inv = __fdividef(1.f, s);
        float z[8];
#pragma unroll
        for (int d = 0; d < 8; d++) z[d] = a[0] * nhf[0][d];
#pragma unroll
        for (int j = 1; j < 4; j++)
#pragma unroll
            for (int d = 0; d < 8; d++) z[d] = fmaf(a[j], nhf[j][d], z[d]);
#pragma unroll
        for (int d = 0; d < 8; d++) {
            z[d] += __shfl_xor_sync(0xffffffffu, z[d], 1);
            z[d] += __shfl_xor_sync(0xffffffffu, z[d], 2);
            ht[d] = fmaf(z[d], inv, cf[d]);
        }
    }
}

__device__ __forceinline__ void load8(const float* __restrict__ p, float v[8]) {
    float4 t0 = __ldg((const float4*)p);
    float4 t1 = __ldg((const float4*)(p + 4));
    v[0] = t0.x; v[1] = t0.y; v[2] = t0.z; v[3] = t0.w;
    v[4] = t1.x; v[5] = t1.y; v[6] = t1.z; v[7] = t1.w;
}

// Select this lane's 2 output dims (dims 2*lane = 8k+2sub) without dynamic
// register indexing.
__device__ __forceinline__ float2 pick2(const float ht[8], int sub) {
    float2 o;
    o.x = (sub == 0) ? ht[0] : (sub == 1) ? ht[2] : (sub == 2) ? ht[4] : ht[6];
    o.y = (sub == 0) ? ht[1] : (sub == 1) ? ht[3] : (sub == 2) ? ht[5] : ht[7];
    return o;
}

// ---------------------------------------------------------------------------
// Fully fused routing. One block per (branch, b): 4096 blocks x 512 threads.
//   phase 1 (16 warps): layer-1 routing for b's 16 sites -> relu -> smem h1
//   phase 2 (16 warps): h1t[s] = h1[s] @ W0n   (W0 staged in smem)
//   phase 3 (warp 0)  : layer-0 routing (center = raw table row) -> d_out
// user branch: l1 center TI[u1], neighbors TU[u2], W0n = Wpre0_item,
//              l0 center user_table[u0].  Item branch symmetric.
// ---------------------------------------------------------------------------
__global__ __launch_bounds__(512, 2) void fused_routing(
        const float* __restrict__ user_table, const float* __restrict__ item_table,
        const float* __restrict__ W0u, const float* __restrict__ W0i,
        const int* __restrict__ u0, const int* __restrict__ u1, const int* __restrict__ u2,
        const int* __restrict__ i0, const int* __restrict__ i1, const int* __restrict__ i2,
        float* __restrict__ out) {
    __shared__ float sW0[64 * 64];
    __shared__ float sh1[NS * 64];
    __shared__ float sh1t[NS * 64];

    const int tid  = threadIdx.x;
    const int warp = tid >> 5;
    const int lane = tid & 31;
    const int branch = (int)blockIdx.x >> 11;
    const int b      = (int)blockIdx.x & 2047;
    const int k = lane >> 2, sub = lane & 3;

    const float* cT; const float* nT; const float* W0; const float* tab0;
    const int* i1p; const int* i2p; const int* i0p;
    if (branch == 0) {
        cT = g_scratch + OFF_TI; nT = g_scratch + OFF_TU;
        i1p = u1; i2p = u2; W0 = W0i; tab0 = user_table; i0p = u0;
    } else {
        cT = g_scratch + OFF_TU; nT = g_scratch + OFF_TI;
        i1p = i1; i2p = i2; W0 = W0u; tab0 = item_table; i0p = i0;
    }
    const int site = b * NS + warp;

    // ---- phase 1 gathers (issued first to maximize MLP) ----
    float cf[8], ht[8], nhf[4][8];
    load8(cT + (long)__ldg(&i1p[site]) * 64 + 8 * k, cf);
#pragma unroll
    for (int j = 0; j < 4; j++)
        load8(nT + (long)__ldg(&i2p[site * 16 + 4 * sub + j]) * 64 + 8 * k, nhf[j]);

    // Stage W0 (16KB, L2-resident) — overlaps with gather latency.
#pragma unroll
    for (int e = tid; e < 1024; e += 512)
        ((float4*)sW0)[e] = __ldg(((const float4*)W0) + e);

    // warp 0 prefetches the layer-0 center (raw table row).
    float cf0[8];
    if (warp == 0)
        load8(tab0 + (long)__ldg(&i0p[b]) * 64 + 8 * k, cf0);

#pragma unroll
    for (int d = 0; d < 8; d++) ht[d] = cf[d];
    routing_core(cf, nhf, ht);
#pragma unroll
    for (int d = 0; d < 8; d++) ht[d] = fmaxf(ht[d], 0.f);   // relu (layer 1)
    {
        float2 o = pick2(ht, sub);
        *(float2*)&sh1[warp * 64 + 2 * lane] = o;
    }
    __syncthreads();

    // ---- phase 2: h1t[warp][c] = sum_d sh1[warp][d] * W0[d][c] ----
    {
        float y0 = 0.f, y1 = 0.f;
        const float* hrow = &sh1[warp * 64];
#pragma unroll 16
        for (int d = 0; d < 64; d++) {
            float h = hrow[d];                               // broadcast
            float2 w = *(const float2*)&sW0[d * 64 + 2 * lane];
            y0 = fmaf(h, w.x, y0);
            y1 = fmaf(h, w.y, y1);
        }
        *(float2*)&sh1t[warp * 64 + 2 * lane] = make_float2(y0, y1);
    }
    __syncthreads();

    // ---- phase 3: layer-0 routing (warp 0 only) ----
    if (warp == 0) {
        float nh0[4][8], ht0[8];
#pragma unroll
        for (int j = 0; j < 4; j++)
#pragma unroll
            for (int d = 0; d < 8; d++)
                nh0[j][d] = sh1t[(4 * sub + j) * 64 + 8 * k + d];
#pragma unroll
        for (int d = 0; d < 8; d++) ht0[d] = cf0[d];
        routing_core(cf0, nh0, ht0);
        float2 o = pick2(ht0, sub);
        *(float2*)&out[((long)branch * NB + b) * 64 + 2 * lane] = o;
    }
}

// ---------------------------------------------------------------------------
// Inputs (metadata order):
//  0 user_table[V,64] 1 item_table[V,64]
//  2 Wpre0_user 3 Wpre0_item 4 Wpre1_user 5 Wpre1_item      (all [64,64] f32)
//  6 user_idx0[B] 7 user_idx1[B,16] 8 user_idx2[B,16,16]    (int32)
//  9 item_idx0    10 item_idx1      11 item_idx2
// Output: f32 [2,2048,64] = (user_h, item_h)
// ---------------------------------------------------------------------------
extern "C" void kernel_launch(void* const* d_in, const int* in_sizes, int n_in,
                              void* d_out, int out_size) {
    const float* user_table = (const float*)d_in[0];
    const float* item_table = (const float*)d_in[1];
    const float* W0u = (const float*)d_in[2];
    const float* W0i = (const float*)d_in[3];
    const float* W1u = (const float*)d_in[4];
    const float* W1i = (const float*)d_in[5];
    const int* u0 = (const int*)d_in[6];
    const int* u1 = (const int*)d_in[7];
    const int* u2 = (const int*)d_in[8];
    const int* i0 = (const int*)d_in[9];
    const int* i1 = (const int*)d_in[10];
    const int* i2 = (const int*)d_in[11];

    const int V   = in_sizes[0] / 64;           // 100000
    const int bph = (V + 127) / 128;            // 782

    // 1: pre-transform both tables in ONE launch
    //    TU = user_table @ W1u ; TI = item_table @ W1i
    gemm64x2<<<2 * bph, 256>>>(user_table, item_table,
                               W1u, W1i, OFF_TU, OFF_TI, V, bph);

    // 2: fully fused routing (layer-1 + W0 matvec + layer-0) -> output
    fused_routing<<<2 * NB, 512>>>(user_table, item_table, W0u, W0i,
                                   u0, u1, u2, i0, i1, i2, (float*)d_out);
    (void)n_in; (void)out_size;
}